// round 2
// baseline (speedup 1.0000x reference)
#include <cuda_runtime.h>
#include <float.h>

// Problem constants
#define Bn 64
#define Hn 28
#define Wn 28
#define Cn 512
#define Sn (Hn * Wn)          // 784 spatial positions
#define CTILE 128             // channels per block (== blockDim.x)

// out[b,s,c] = relu( x[b,s,c] * t_p[b, argmax_s' x[b,s',c], s] )
__global__ __launch_bounds__(CTILE, 8)
void masked_output_kernel(const float* __restrict__ x,
                          const float* __restrict__ tp,
                          float* __restrict__ out)
{
    const int b = blockIdx.y;
    const int c = blockIdx.x * CTILE + threadIdx.x;

    const float* xb = x + (size_t)b * Sn * Cn + c;   // column (b, :, c), stride Cn

    // ---------------- Pass 1: argmax over s (first-max tie-break) ----------------
    float best = -FLT_MAX;
    int   bi   = 0;
    #pragma unroll 8
    for (int s = 0; s < Sn; s++) {
        float v = __ldcs(xb + (size_t)s * Cn);   // streaming: one-time scan
        if (v > best) { best = v; bi = s; }
    }

    // Template row for this (b,c): contiguous 784 floats, 16B-aligned (784*4 % 16 == 0)
    const float4* __restrict__ t4 =
        reinterpret_cast<const float4*>(tp + (size_t)b * Sn * Sn + (size_t)bi * Sn);

    float* ob = out + (size_t)b * Sn * Cn + c;

    // ---------------- Pass 2: fused gather + multiply + relu ----------------
    // Each iteration: 1 per-thread float4 template load (L1-streamed),
    // 4 warp-coalesced x loads, 4 warp-coalesced streaming stores.
    #pragma unroll 2
    for (int s4 = 0; s4 < Sn / 4; s4++) {
        float4 t = __ldg(t4 + s4);
        int s = s4 * 4;
        float r0 = fmaxf(xb[(size_t)(s + 0) * Cn] * t.x, 0.0f);
        float r1 = fmaxf(xb[(size_t)(s + 1) * Cn] * t.y, 0.0f);
        float r2 = fmaxf(xb[(size_t)(s + 2) * Cn] * t.z, 0.0f);
        float r3 = fmaxf(xb[(size_t)(s + 3) * Cn] * t.w, 0.0f);
        __stcs(ob + (size_t)(s + 0) * Cn, r0);
        __stcs(ob + (size_t)(s + 1) * Cn, r1);
        __stcs(ob + (size_t)(s + 2) * Cn, r2);
        __stcs(ob + (size_t)(s + 3) * Cn, r3);
    }
}

extern "C" void kernel_launch(void* const* d_in, const int* in_sizes, int n_in,
                              void* d_out, int out_size)
{
    const float* x  = (const float*)d_in[0];   // [B, H, W, C]
    const float* tp = (const float*)d_in[1];   // [B, H, W, H, W]
    float* out = (float*)d_out;                // [B, H, W, C]

    dim3 grid(Cn / CTILE, Bn);   // (4, 64) = 256 blocks
    masked_output_kernel<<<grid, CTILE>>>(x, tp, out);
}

// round 3
// speedup vs baseline: 2.7609x; 2.7609x over previous
#include <cuda_runtime.h>
#include <float.h>

#define Bn 64
#define Hn 28
#define Wn 28
#define Cn 512
#define Sn (Hn * Wn)          // 784
#define CT 128                // channels per block
#define SY 8                  // s-groups per block in argmax kernel (784 = 8*98)
#define SSPLIT 14             // s-chunks in apply kernel (784 = 14*56)
#define SCHUNK (Sn / SSPLIT)  // 56

// scratch: argmax spatial index per (b, c)
__device__ int g_idx[Bn * Cn];

// ---------------- Kernel 1: per-(b,c) argmax over s ----------------
__global__ __launch_bounds__(CT * SY, 1)
void argmax_kernel(const float* __restrict__ x)
{
    __shared__ float sval[SY][CT];
    __shared__ int   sidx[SY][CT];

    const int b  = blockIdx.y;
    const int tx = threadIdx.x;
    const int ty = threadIdx.y;
    const int c  = blockIdx.x * CT + tx;

    const float* xb = x + (size_t)b * Sn * Cn + c;

    // thread owns s ≡ ty (mod SY); scan ascending with strict > (first-max kept)
    float best = -FLT_MAX;
    int   bi   = ty;
    #pragma unroll 7
    for (int s = ty; s < Sn; s += SY) {
        float v = __ldcs(xb + (size_t)s * Cn);
        if (v > best) { best = v; bi = s; }
    }

    sval[ty][tx] = best;
    sidx[ty][tx] = bi;
    __syncthreads();

    if (ty == 0) {
        // combine partials: on tie, smaller index wins (jnp.argmax semantics)
        #pragma unroll
        for (int k = 1; k < SY; k++) {
            float v = sval[k][tx];
            int   i = sidx[k][tx];
            if (v > best || (v == best && i < bi)) { best = v; bi = i; }
        }
        g_idx[b * Cn + c] = bi;
    }
}

// ---------------- Kernel 2: out = relu(x * gathered template) ----------------
__global__ __launch_bounds__(CT, 16)
void apply_kernel(const float* __restrict__ x,
                  const float* __restrict__ tp,
                  float* __restrict__ out)
{
    const int b  = blockIdx.y;
    const int c  = blockIdx.x * CT + threadIdx.x;
    const int s0 = blockIdx.z * SCHUNK;

    const int bi = g_idx[b * Cn + c];

    const float* xb = x + (size_t)b * Sn * Cn + c;
    float*       ob = out + (size_t)b * Sn * Cn + c;
    // template row contiguous; s0*4 = 224 B and row stride 3136 B are 16B-aligned
    const float4* __restrict__ t4 =
        reinterpret_cast<const float4*>(tp + ((size_t)b * Sn + bi) * Sn + s0);

    #pragma unroll
    for (int k = 0; k < SCHUNK / 4; k++) {
        float4 t = __ldg(t4 + k);
        int s = s0 + 4 * k;
        float r0 = fmaxf(xb[(size_t)(s + 0) * Cn] * t.x, 0.0f);
        float r1 = fmaxf(xb[(size_t)(s + 1) * Cn] * t.y, 0.0f);
        float r2 = fmaxf(xb[(size_t)(s + 2) * Cn] * t.z, 0.0f);
        float r3 = fmaxf(xb[(size_t)(s + 3) * Cn] * t.w, 0.0f);
        __stcs(ob + (size_t)(s + 0) * Cn, r0);
        __stcs(ob + (size_t)(s + 1) * Cn, r1);
        __stcs(ob + (size_t)(s + 2) * Cn, r2);
        __stcs(ob + (size_t)(s + 3) * Cn, r3);
    }
}

extern "C" void kernel_launch(void* const* d_in, const int* in_sizes, int n_in,
                              void* d_out, int out_size)
{
    const float* x  = (const float*)d_in[0];   // [B, H, W, C]
    const float* tp = (const float*)d_in[1];   // [B, H, W, H, W]
    float* out = (float*)d_out;                // [B, H, W, C]

    dim3 grid1(Cn / CT, Bn);            // (4, 64)
    dim3 block1(CT, SY);                // 1024 threads
    argmax_kernel<<<grid1, block1>>>(x);

    dim3 grid2(Cn / CT, Bn, SSPLIT);    // (4, 64, 14) = 3584 blocks
    apply_kernel<<<grid2, CT>>>(x, tp, out);
}